// round 1
// baseline (speedup 1.0000x reference)
#include <cuda_runtime.h>
#include <math.h>

#define BSZ   8
#define HD    128
#define LSEQ  8192
#define PD    256
#define CS    128           // scan chunk length
#define NC    (LSEQ / CS)   // 64 chunks

// Scratch (allowed: __device__ globals). g_bu layout: (b, l, p) interleaved complex.
__device__ __align__(16) float2 g_bu[(size_t)BSZ * LSEQ * PD];     // 128 MB
__device__ __align__(16) float2 g_E[BSZ * NC * PD];                 // chunk-local end states
__device__ __align__(16) float2 g_carry[BSZ * NC * PD];             // carry-in per chunk

__device__ __forceinline__ float2 cmulf(float2 a, float2 b) {
    return make_float2(a.x * b.x - a.y * b.y, a.x * b.y + a.y * b.x);
}

// ---------------------------------------------------------------------------
// K1: g_bu[b,l,p] = Lambda_bar[p] * sum_h B_bar[p,h] * u[b,h,l]   (complex)
// Block: 256 threads, tile = 64 p x 128 l. Thread tile = 4 p x 8 l.
// grid = (LSEQ/128, PD/64, BSZ)
// ---------------------------------------------------------------------------
__global__ void __launch_bounds__(256) k1_bu(
    const float* __restrict__ u,
    const float* __restrict__ Are, const float* __restrict__ Aim,
    const float* __restrict__ Bre, const float* __restrict__ Bim)
{
    __shared__ float  su[128][17];    // [l][h]  (pad 17 -> conflict-free strided reads)
    __shared__ float2 sw[64][17];     // [p][h]

    const int b     = blockIdx.z;
    const int lbase = blockIdx.x * 128;
    const int pbase = blockIdx.y * 64;
    const int tid   = threadIdx.x;
    const int tp    = tid & 15;   // 16 p-groups of 4
    const int tl    = tid >> 4;   // 16 l-groups of 8

    float2 acc[4][8];
#pragma unroll
    for (int i = 0; i < 4; i++)
#pragma unroll
        for (int j = 0; j < 8; j++) acc[i][j] = make_float2(0.f, 0.f);

    for (int h0 = 0; h0 < HD; h0 += 16) {
        __syncthreads();
        // stage u tile: 16 h x 128 l (coalesced over l)
        for (int idx = tid; idx < 16 * 128; idx += 256) {
            int i = idx >> 7, j = idx & 127;
            su[j][i] = u[(b * HD + h0 + i) * LSEQ + lbase + j];
        }
        // stage W tile: 64 p x 16 h (coalesced over h)
        for (int idx = tid; idx < 64 * 16; idx += 256) {
            int pp = idx >> 4, i = idx & 15;
            int gi = (pbase + pp) * HD + h0 + i;
            sw[pp][i] = make_float2(Bre[gi], Bim[gi]);
        }
        __syncthreads();

#pragma unroll
        for (int hh = 0; hh < 16; hh++) {
            float2 w[4];
            float  uu[8];
#pragma unroll
            for (int i = 0; i < 4; i++) w[i] = sw[tp * 4 + i][hh];
#pragma unroll
            for (int j = 0; j < 8; j++) uu[j] = su[tl * 8 + j][hh];
#pragma unroll
            for (int i = 0; i < 4; i++)
#pragma unroll
                for (int j = 0; j < 8; j++) {
                    acc[i][j].x = fmaf(w[i].x, uu[j], acc[i][j].x);
                    acc[i][j].y = fmaf(w[i].y, uu[j], acc[i][j].y);
                }
        }
    }

    // epilogue: multiply by Lambda_bar, vectorized store (lanes contiguous in p)
    float2 a[4];
#pragma unroll
    for (int i = 0; i < 4; i++) {
        int p = pbase + tp * 4 + i;
        a[i] = make_float2(Are[p], Aim[p]);
    }
#pragma unroll
    for (int j = 0; j < 8; j++) {
        float2 o0 = cmulf(a[0], acc[0][j]);
        float2 o1 = cmulf(a[1], acc[1][j]);
        float2 o2 = cmulf(a[2], acc[2][j]);
        float2 o3 = cmulf(a[3], acc[3][j]);
        int base = ((b * LSEQ + lbase + tl * 8 + j) * PD) + pbase + tp * 4;
        float4* dst = reinterpret_cast<float4*>(&g_bu[base]);
        dst[0] = make_float4(o0.x, o0.y, o1.x, o1.y);
        dst[1] = make_float4(o2.x, o2.y, o3.x, o3.y);
    }
}

// ---------------------------------------------------------------------------
// K2a: chunk-local scan (zero init), store final state E.  x_t = A x_{t-1} + bu'_t
// grid = (NC, BSZ), 256 threads (one per p). g_bu reads coalesced over p.
// ---------------------------------------------------------------------------
__global__ void __launch_bounds__(256) k2a_local(
    const float* __restrict__ Are, const float* __restrict__ Aim)
{
    const int b = blockIdx.y, c = blockIdx.x, p = threadIdx.x;
    const float2 a = make_float2(Are[p], Aim[p]);
    float2 x = make_float2(0.f, 0.f);
    int idx = (b * LSEQ + c * CS) * PD + p;
#pragma unroll 4
    for (int l = 0; l < CS; l++) {
        float2 bu = g_bu[idx];
        idx += PD;
        float nx = fmaf(a.x, x.x, fmaf(-a.y, x.y, bu.x));
        float ny = fmaf(a.x, x.y, fmaf( a.y, x.x, bu.y));
        x = make_float2(nx, ny);
    }
    g_E[(b * NC + c) * PD + p] = x;
}

// ---------------------------------------------------------------------------
// K2b: sequential carry scan across chunks. S_{c+1} = A^CS * S_c + E_c, carry[c]=S_c.
// grid = BSZ blocks x 256 threads.
// ---------------------------------------------------------------------------
__global__ void __launch_bounds__(256) k2b_carry(
    const float* __restrict__ Are, const float* __restrict__ Aim)
{
    const int b = blockIdx.x, p = threadIdx.x;
    float2 a = make_float2(Are[p], Aim[p]);
    float2 aT = a;                        // A^CS, CS = 128 = 2^7
#pragma unroll
    for (int k = 0; k < 7; k++) aT = cmulf(aT, aT);
    float2 S = make_float2(0.f, 0.f);
    for (int c = 0; c < NC; c++) {
        int i = (b * NC + c) * PD + p;
        g_carry[i] = S;
        float2 E = g_E[i];
        float nx = fmaf(aT.x, S.x, fmaf(-aT.y, S.y, E.x));
        float ny = fmaf(aT.x, S.y, fmaf( aT.y, S.x, E.y));
        S = make_float2(nx, ny);
    }
}

// ---------------------------------------------------------------------------
// K2c: replay chunk scan with carry, write x in place of bu'.
// ---------------------------------------------------------------------------
__global__ void __launch_bounds__(256) k2c_replay(
    const float* __restrict__ Are, const float* __restrict__ Aim)
{
    const int b = blockIdx.y, c = blockIdx.x, p = threadIdx.x;
    const float2 a = make_float2(Are[p], Aim[p]);
    float2 x = g_carry[(b * NC + c) * PD + p];
    int idx = (b * LSEQ + c * CS) * PD + p;
#pragma unroll 4
    for (int l = 0; l < CS; l++) {
        float2 bu = g_bu[idx];
        float nx = fmaf(a.x, x.x, fmaf(-a.y, x.y, bu.x));
        float ny = fmaf(a.x, x.y, fmaf( a.y, x.x, bu.y));
        x = make_float2(nx, ny);
        g_bu[idx] = x;
        idx += PD;
    }
}

// ---------------------------------------------------------------------------
// K3: out[b,o,l] = gelu( Re(sum_p C[o,p] x[b,l,p]) + sum_h D[o,h] u[b,h,l] )
// Block: 256 threads, tile = 128 o x 128 l. Thread tile = 8 o x 8 l.
// grid = (LSEQ/128, BSZ)
// ---------------------------------------------------------------------------
__global__ void __launch_bounds__(256) k3_out(
    const float* __restrict__ u,
    const float* __restrict__ Cre, const float* __restrict__ Cim,
    const float* __restrict__ Dm,  float* __restrict__ out)
{
    __shared__ float2 sx[128][17];   // [l][pp]  (x tile)
    __shared__ float2 sc[128][17];   // [o][pp]  (C tile)

    const int b     = blockIdx.y;
    const int lbase = blockIdx.x * 128;
    const int tid   = threadIdx.x;
    const int tl    = tid & 15;   // 16 l-groups of 8
    const int to    = tid >> 4;   // 16 o-groups of 8

    float acc[8][8];
#pragma unroll
    for (int i = 0; i < 8; i++)
#pragma unroll
        for (int j = 0; j < 8; j++) acc[i][j] = 0.f;

    // ---- C @ x over p in tiles of 16 ----
    for (int p0 = 0; p0 < PD; p0 += 16) {
        __syncthreads();
        for (int idx = tid; idx < 16 * 128; idx += 256) {
            int pp = idx & 15, lr = idx >> 4;
            sx[lr][pp] = g_bu[(b * LSEQ + lbase + lr) * PD + p0 + pp];
        }
        for (int idx = tid; idx < 16 * 128; idx += 256) {
            int pp = idx & 15, oo = idx >> 4;
            int gi = oo * PD + p0 + pp;
            sc[oo][pp] = make_float2(Cre[gi], Cim[gi]);
        }
        __syncthreads();

#pragma unroll
        for (int pp = 0; pp < 16; pp++) {
            float2 cf[8], xf[8];
#pragma unroll
            for (int i = 0; i < 8; i++) cf[i] = sc[to * 8 + i][pp];
#pragma unroll
            for (int j = 0; j < 8; j++) xf[j] = sx[tl * 8 + j][pp];
#pragma unroll
            for (int i = 0; i < 8; i++)
#pragma unroll
                for (int j = 0; j < 8; j++) {
                    acc[i][j] = fmaf( cf[i].x, xf[j].x, acc[i][j]);
                    acc[i][j] = fmaf(-cf[i].y, xf[j].y, acc[i][j]);
                }
        }
    }

    // ---- D @ u over h in tiles of 16 (reuse smem) ----
    float* suf = reinterpret_cast<float*>(&sx[0][0]);   // [l][h], stride 17
    float* sdf = reinterpret_cast<float*>(&sc[0][0]);   // [o][h], stride 17
    for (int h0 = 0; h0 < HD; h0 += 16) {
        __syncthreads();
        for (int idx = tid; idx < 16 * 128; idx += 256) {
            int j = idx & 127, hh = idx >> 7;
            suf[j * 17 + hh] = u[(b * HD + h0 + hh) * LSEQ + lbase + j];
        }
        for (int idx = tid; idx < 16 * 128; idx += 256) {
            int hh = idx & 15, oo = idx >> 4;
            sdf[oo * 17 + hh] = Dm[oo * HD + h0 + hh];
        }
        __syncthreads();

#pragma unroll
        for (int hh = 0; hh < 16; hh++) {
            float df[8], uf[8];
#pragma unroll
            for (int i = 0; i < 8; i++) df[i] = sdf[(to * 8 + i) * 17 + hh];
#pragma unroll
            for (int j = 0; j < 8; j++) uf[j] = suf[(tl * 8 + j) * 17 + hh];
#pragma unroll
            for (int i = 0; i < 8; i++)
#pragma unroll
                for (int j = 0; j < 8; j++)
                    acc[i][j] = fmaf(df[i], uf[j], acc[i][j]);
        }
    }

    // ---- exact-erf GELU + vectorized store ----
#pragma unroll
    for (int i = 0; i < 8; i++) {
        int o = to * 8 + i;
        float r[8];
#pragma unroll
        for (int j = 0; j < 8; j++) {
            float y = acc[i][j];
            r[j] = 0.5f * y * (1.f + erff(y * 0.70710678118654752f));
        }
        int base = (b * HD + o) * LSEQ + lbase + tl * 8;
        float4* dst = reinterpret_cast<float4*>(out + base);
        dst[0] = make_float4(r[0], r[1], r[2], r[3]);
        dst[1] = make_float4(r[4], r[5], r[6], r[7]);
    }
}

// ---------------------------------------------------------------------------
extern "C" void kernel_launch(void* const* d_in, const int* in_sizes, int n_in,
                              void* d_out, int out_size)
{
    (void)in_sizes; (void)n_in; (void)out_size;
    const float* u   = (const float*)d_in[0];
    const float* Are = (const float*)d_in[1];
    const float* Aim = (const float*)d_in[2];
    const float* Bre = (const float*)d_in[3];
    const float* Bim = (const float*)d_in[4];
    const float* Cre = (const float*)d_in[5];
    const float* Cim = (const float*)d_in[6];
    const float* Dm  = (const float*)d_in[7];
    float* out = (float*)d_out;

    k1_bu     <<<dim3(LSEQ / 128, PD / 64, BSZ), 256>>>(u, Are, Aim, Bre, Bim);
    k2a_local <<<dim3(NC, BSZ), 256>>>(Are, Aim);
    k2b_carry <<<BSZ, 256>>>(Are, Aim);
    k2c_replay<<<dim3(NC, BSZ), 256>>>(Are, Aim);
    k3_out    <<<dim3(LSEQ / 128, BSZ), 256>>>(u, Cre, Cim, Dm, out);
}

// round 2
// speedup vs baseline: 1.6327x; 1.6327x over previous
#include <cuda_runtime.h>
#include <cuda_bf16.h>
#include <math.h>

#define BSZ   8
#define HD    128
#define LSEQ  8192
#define PD    256
#define NC2   16
#define CL    (LSEQ / NC2)   // 512 per chunk

// ---------------- scratch (__device__ globals) ----------------
__device__ __align__(16) float g_br[(size_t)BSZ * PD * LSEQ];   // Bu real -> x real (in place)
__device__ __align__(16) float g_bi[(size_t)BSZ * PD * LSEQ];   // Bu imag -> x imag (in place)
__device__ float2 g_E[BSZ * NC2 * PD];
__device__ float2 g_carry[BSZ * NC2 * PD];
__device__ __nv_bfloat16 g_Wb_hi[512 * 128], g_Wb_lo[512 * 128];  // [Bre;Bim] row-major [m][k]
__device__ __nv_bfloat16 g_Wc_hi[128 * 640], g_Wc_lo[128 * 640];  // [Cre|-Cim|D] [o][k]

__device__ __forceinline__ float2 cmul(float2 a, float2 b) {
    return make_float2(a.x * b.x - a.y * b.y, a.x * b.y + a.y * b.x);
}
__device__ __forceinline__ void split2(float v, __nv_bfloat16* hi, __nv_bfloat16* lo) {
    __nv_bfloat16 h = __float2bfloat16(v);
    *hi = h;
    *lo = __float2bfloat16(v - __bfloat162float(h));
}
__device__ __forceinline__ void mma_bf16(float c[4], const unsigned a[4], const unsigned b[2]) {
    asm volatile(
        "mma.sync.aligned.m16n8k16.row.col.f32.bf16.bf16.f32 "
        "{%0,%1,%2,%3}, {%4,%5,%6,%7}, {%8,%9}, {%0,%1,%2,%3};"
        : "+f"(c[0]), "+f"(c[1]), "+f"(c[2]), "+f"(c[3])
        : "r"(a[0]), "r"(a[1]), "r"(a[2]), "r"(a[3]), "r"(b[0]), "r"(b[1]));
}

// ---------------------------------------------------------------------------
// K0: split weights to bf16 hi/lo
// ---------------------------------------------------------------------------
__global__ void __launch_bounds__(256) k0_prep(
    const float* __restrict__ Bre, const float* __restrict__ Bim,
    const float* __restrict__ Cre, const float* __restrict__ Cim,
    const float* __restrict__ Dm)
{
    int i = blockIdx.x * 256 + threadIdx.x;
    if (i < 512 * 128) {
        int m = i >> 7, k = i & 127;
        float w = (m < 256) ? Bre[m * 128 + k] : Bim[(m - 256) * 128 + k];
        split2(w, &g_Wb_hi[i], &g_Wb_lo[i]);
    }
    if (i < 128 * 640) {
        int o = i / 640, k = i % 640;
        float w = (k < 256) ? Cre[o * 256 + k]
                 : (k < 512 ? -Cim[o * 256 + (k - 256)] : Dm[o * 128 + (k - 512)]);
        split2(w, &g_Wc_hi[i], &g_Wc_lo[i]);
    }
}

// ---------------------------------------------------------------------------
// K1: Bu planes = [Bre;Bim](512x128) @ u(128 x L) per batch, bf16-split mma.
// Block 256 thr (8 warps, 4m x 2n), tile 128m x 128l, K=128 in 2 chunks of 64.
// grid = (L/128, 512/128, BSZ)
// ---------------------------------------------------------------------------
__global__ void __launch_bounds__(256) k1_bu(const float* __restrict__ u)
{
    __shared__ __nv_bfloat16 sh[128][72];   // [l][k] hi
    __shared__ __nv_bfloat16 sl[128][72];   // [l][k] lo

    const int b     = blockIdx.z;
    const int lbase = blockIdx.x * 128;
    const int mbase = blockIdx.y * 128;
    const int tid   = threadIdx.x;
    const int lane  = tid & 31, wid = tid >> 5;
    const int wm    = wid >> 1, wn = wid & 1;

    float c[2][8][4];
#pragma unroll
    for (int mi = 0; mi < 2; mi++)
#pragma unroll
        for (int ni = 0; ni < 8; ni++)
#pragma unroll
            for (int q = 0; q < 4; q++) c[mi][ni][q] = 0.f;

    for (int kc = 0; kc < 128; kc += 64) {
        __syncthreads();
        // stage 64 k-rows x 128 l, transpose + split to bf16
        for (int i = tid; i < 64 * 32; i += 256) {
            int rr = i >> 5;
            int l4 = (i & 31) << 2;
            float4 v = *(const float4*)(u + ((size_t)b * HD + kc + rr) * LSEQ + lbase + l4);
            split2(v.x, &sh[l4 + 0][rr], &sl[l4 + 0][rr]);
            split2(v.y, &sh[l4 + 1][rr], &sl[l4 + 1][rr]);
            split2(v.z, &sh[l4 + 2][rr], &sl[l4 + 2][rr]);
            split2(v.w, &sh[l4 + 3][rr], &sl[l4 + 3][rr]);
        }
        __syncthreads();

#pragma unroll
        for (int ks = 0; ks < 4; ks++) {
            const int kg = kc + ks * 16;             // global k
            const int km = ks * 16;                  // k within smem chunk
            unsigned ah[2][4], al[2][4];
#pragma unroll
            for (int mi = 0; mi < 2; mi++) {
                int row = mbase + wm * 32 + mi * 16 + (lane >> 2);
                int col = kg + (lane & 3) * 2;
                ah[mi][0] = *(const unsigned*)&g_Wb_hi[row * 128 + col];
                ah[mi][1] = *(const unsigned*)&g_Wb_hi[(row + 8) * 128 + col];
                ah[mi][2] = *(const unsigned*)&g_Wb_hi[row * 128 + col + 8];
                ah[mi][3] = *(const unsigned*)&g_Wb_hi[(row + 8) * 128 + col + 8];
                al[mi][0] = *(const unsigned*)&g_Wb_lo[row * 128 + col];
                al[mi][1] = *(const unsigned*)&g_Wb_lo[(row + 8) * 128 + col];
                al[mi][2] = *(const unsigned*)&g_Wb_lo[row * 128 + col + 8];
                al[mi][3] = *(const unsigned*)&g_Wb_lo[(row + 8) * 128 + col + 8];
            }
#pragma unroll
            for (int ni = 0; ni < 8; ni++) {
                int n  = wn * 64 + ni * 8 + (lane >> 2);
                int kk = km + (lane & 3) * 2;
                unsigned bh[2], bl[2];
                bh[0] = *(const unsigned*)&sh[n][kk];
                bh[1] = *(const unsigned*)&sh[n][kk + 8];
                bl[0] = *(const unsigned*)&sl[n][kk];
                bl[1] = *(const unsigned*)&sl[n][kk + 8];
#pragma unroll
                for (int mi = 0; mi < 2; mi++) {
                    mma_bf16(c[mi][ni], ah[mi], bh);
                    mma_bf16(c[mi][ni], ah[mi], bl);
                    mma_bf16(c[mi][ni], al[mi], bh);
                }
            }
        }
    }

    // epilogue: planar float2 stores along l
#pragma unroll
    for (int mi = 0; mi < 2; mi++) {
#pragma unroll
        for (int ni = 0; ni < 8; ni++) {
            int r0 = mbase + wm * 32 + mi * 16 + (lane >> 2);
            int col = lbase + wn * 64 + ni * 8 + (lane & 3) * 2;
            {
                float* plane = (r0 < 256) ? g_br : g_bi;
                int pr = (r0 < 256) ? r0 : r0 - 256;
                *(float2*)&plane[((size_t)b * PD + pr) * LSEQ + col] =
                    make_float2(c[mi][ni][0], c[mi][ni][1]);
            }
            int r1 = r0 + 8;
            {
                float* plane = (r1 < 256) ? g_br : g_bi;
                int pr = (r1 < 256) ? r1 : r1 - 256;
                *(float2*)&plane[((size_t)b * PD + pr) * LSEQ + col] =
                    make_float2(c[mi][ni][2], c[mi][ni][3]);
            }
        }
    }
}

// ---------------------------------------------------------------------------
// K2 warp-scan: x_t = a*x_{t-1} + a*Bu_t along l (coalesced in planar layout).
// Within a 32-segment: w_i = Bu_i * a^{1-i}; S = inclusive prefix(w);
// x_i = a^i * (a*carry + S_i).
// ---------------------------------------------------------------------------
__device__ __forceinline__ void lane_powers(float2 a, int lane,
                                            float2* ap, float2* w1m)
{
    float invn = 1.f / (a.x * a.x + a.y * a.y);
    float2 ainv = make_float2(a.x * invn, -a.y * invn);
    float2 pp = make_float2(1.f, 0.f), pn = make_float2(1.f, 0.f);
    float2 t = a, ti = ainv;
#pragma unroll
    for (int bit = 1; bit < 32; bit <<= 1) {
        if (lane & bit) { pp = cmul(pp, t); pn = cmul(pn, ti); }
        t = cmul(t, t); ti = cmul(ti, ti);
    }
    *ap  = pp;            // a^i
    *w1m = cmul(a, pn);   // a^{1-i}
}

template <bool WRITE_X, bool LOAD_CARRY>
__device__ __forceinline__ void scan_chunk(
    const float* Are, const float* Aim)
{
    const int b = blockIdx.z, c = blockIdx.x;
    const int wid = threadIdx.x >> 5, lane = threadIdx.x & 31;
    const int p = blockIdx.y * 8 + wid;
    const float2 a = make_float2(Are[p], Aim[p]);
    float2 ap, w1m;
    lane_powers(a, lane, &ap, &w1m);

    const size_t base = ((size_t)b * PD + p) * LSEQ + (size_t)c * CL;
    float2 carry = make_float2(0.f, 0.f);
    if (LOAD_CARRY) carry = g_carry[(b * NC2 + c) * PD + p];

#pragma unroll 4
    for (int s = 0; s < CL / 32; s++) {
        size_t idx = base + s * 32 + lane;
        float br = g_br[idx], bi = g_bi[idx];
        float2 w = make_float2(br * w1m.x - bi * w1m.y, br * w1m.y + bi * w1m.x);
#pragma unroll
        for (int d = 1; d < 32; d <<= 1) {
            float ox = __shfl_up_sync(0xffffffffu, w.x, d);
            float oy = __shfl_up_sync(0xffffffffu, w.y, d);
            if (lane >= d) { w.x += ox; w.y += oy; }
        }
        float2 ac = cmul(a, carry);
        float2 x  = cmul(ap, make_float2(ac.x + w.x, ac.y + w.y));
        if (WRITE_X) { g_br[idx] = x.x; g_bi[idx] = x.y; }
        carry.x = __shfl_sync(0xffffffffu, x.x, 31);
        carry.y = __shfl_sync(0xffffffffu, x.y, 31);
    }
    if (!WRITE_X && lane == 0)
        g_E[(b * NC2 + c) * PD + p] = carry;
}

__global__ void __launch_bounds__(256) k2a_local(
    const float* __restrict__ Are, const float* __restrict__ Aim)
{ scan_chunk<false, false>(Are, Aim); }

__global__ void __launch_bounds__(256) k2c_replay(
    const float* __restrict__ Are, const float* __restrict__ Aim)
{ scan_chunk<true, true>(Are, Aim); }

__global__ void __launch_bounds__(256) k2b_carry(
    const float* __restrict__ Are, const float* __restrict__ Aim)
{
    const int b = blockIdx.x, p = threadIdx.x;
    float2 a = make_float2(Are[p], Aim[p]);
    float2 aT = a;
#pragma unroll
    for (int k = 0; k < 9; k++) aT = cmul(aT, aT);   // a^512 = a^CL
    float2 S = make_float2(0.f, 0.f);
    for (int c = 0; c < NC2; c++) {
        int i = (b * NC2 + c) * PD + p;
        g_carry[i] = S;
        float2 E = g_E[i];
        S = make_float2(aT.x * S.x - aT.y * S.y + E.x,
                        aT.x * S.y + aT.y * S.x + E.y);
    }
}

// ---------------------------------------------------------------------------
// K3: out = gelu( [Cre|-Cim|D](128x640) @ [x_re; x_im; u](640 x L) ) per batch.
// Block 256 thr (8 warps, 4m x 2n), tile 128o x 128l, K=640 in 10 chunks of 64.
// grid = (L/128, BSZ)
// ---------------------------------------------------------------------------
__global__ void __launch_bounds__(256) k3_out(const float* __restrict__ u,
                                              float* __restrict__ out)
{
    __shared__ __nv_bfloat16 sh[128][72];
    __shared__ __nv_bfloat16 sl[128][72];

    const int b     = blockIdx.y;
    const int lbase = blockIdx.x * 128;
    const int tid   = threadIdx.x;
    const int lane  = tid & 31, wid = tid >> 5;
    const int wm    = wid >> 1, wn = wid & 1;

    float c[2][8][4];
#pragma unroll
    for (int mi = 0; mi < 2; mi++)
#pragma unroll
        for (int ni = 0; ni < 8; ni++)
#pragma unroll
            for (int q = 0; q < 4; q++) c[mi][ni][q] = 0.f;

    for (int kc = 0; kc < 640; kc += 64) {
        const float* src;
        if (kc < 256)      src = g_br + ((size_t)b * PD + kc) * LSEQ;
        else if (kc < 512) src = g_bi + ((size_t)b * PD + (kc - 256)) * LSEQ;
        else               src = u    + ((size_t)b * HD + (kc - 512)) * LSEQ;

        __syncthreads();
        for (int i = tid; i < 64 * 32; i += 256) {
            int rr = i >> 5;
            int l4 = (i & 31) << 2;
            float4 v = *(const float4*)(src + (size_t)rr * LSEQ + lbase + l4);
            split2(v.x, &sh[l4 + 0][rr], &sl[l4 + 0][rr]);
            split2(v.y, &sh[l4 + 1][rr], &sl[l4 + 1][rr]);
            split2(v.z, &sh[l4 + 2][rr], &sl[l4 + 2][rr]);
            split2(v.w, &sh[l4 + 3][rr], &sl[l4 + 3][rr]);
        }
        __syncthreads();

#pragma unroll
        for (int ks = 0; ks < 4; ks++) {
            const int kg = kc + ks * 16;
            const int km = ks * 16;
            unsigned ah[2][4], al[2][4];
#pragma unroll
            for (int mi = 0; mi < 2; mi++) {
                int row = wm * 32 + mi * 16 + (lane >> 2);
                int col = kg + (lane & 3) * 2;
                ah[mi][0] = *(const unsigned*)&g_Wc_hi[row * 640 + col];
                ah[mi][1] = *(const unsigned*)&g_Wc_hi[(row + 8) * 640 + col];
                ah[mi][2] = *(const unsigned*)&g_Wc_hi[row * 640 + col + 8];
                ah[mi][3] = *(const unsigned*)&g_Wc_hi[(row + 8) * 640 + col + 8];
                al[mi][0] = *(const unsigned*)&g_Wc_lo[row * 640 + col];
                al[mi][1] = *(const unsigned*)&g_Wc_lo[(row + 8) * 640 + col];
                al[mi][2] = *(const unsigned*)&g_Wc_lo[row * 640 + col + 8];
                al[mi][3] = *(const unsigned*)&g_Wc_lo[(row + 8) * 640 + col + 8];
            }
#pragma unroll
            for (int ni = 0; ni < 8; ni++) {
                int n  = wn * 64 + ni * 8 + (lane >> 2);
                int kk = km + (lane & 3) * 2;
                unsigned bh[2], bl[2];
                bh[0] = *(const unsigned*)&sh[n][kk];
                bh[1] = *(const unsigned*)&sh[n][kk + 8];
                bl[0] = *(const unsigned*)&sl[n][kk];
                bl[1] = *(const unsigned*)&sl[n][kk + 8];
#pragma unroll
                for (int mi = 0; mi < 2; mi++) {
                    mma_bf16(c[mi][ni], ah[mi], bh);
                    mma_bf16(c[mi][ni], ah[mi], bl);
                    mma_bf16(c[mi][ni], al[mi], bh);
                }
            }
        }
    }

    // epilogue: exact-erf GELU, float2 stores along l
#pragma unroll
    for (int mi = 0; mi < 2; mi++) {
#pragma unroll
        for (int ni = 0; ni < 8; ni++) {
            int r0  = wm * 32 + mi * 16 + (lane >> 2);
            int col = lbase + wn * 64 + ni * 8 + (lane & 3) * 2;
            float y0 = c[mi][ni][0], y1 = c[mi][ni][1];
            float y2 = c[mi][ni][2], y3 = c[mi][ni][3];
            y0 = 0.5f * y0 * (1.f + erff(y0 * 0.70710678118654752f));
            y1 = 0.5f * y1 * (1.f + erff(y1 * 0.70710678118654752f));
            y2 = 0.5f * y2 * (1.f + erff(y2 * 0.70710678118654752f));
            y3 = 0.5f * y3 * (1.f + erff(y3 * 0.70710678118654752f));
            *(float2*)&out[((size_t)b * HD + r0) * LSEQ + col]       = make_float2(y0, y1);
            *(float2*)&out[((size_t)b * HD + r0 + 8) * LSEQ + col]   = make_float2(y2, y3);
        }
    }
}

// ---------------------------------------------------------------------------
extern "C" void kernel_launch(void* const* d_in, const int* in_sizes, int n_in,
                              void* d_out, int out_size)
{
    (void)in_sizes; (void)n_in; (void)out_size;
    const float* u   = (const float*)d_in[0];
    const float* Are = (const float*)d_in[1];
    const float* Aim = (const float*)d_in[2];
    const float* Bre = (const float*)d_in[3];
    const float* Bim = (const float*)d_in[4];
    const float* Cre = (const float*)d_in[5];
    const float* Cim = (const float*)d_in[6];
    const float* Dm  = (const float*)d_in[7];
    float* out = (float*)d_out;

    k0_prep   <<<320, 256>>>(Bre, Bim, Cre, Cim, Dm);
    k1_bu     <<<dim3(LSEQ / 128, 4, BSZ), 256>>>(u);
    k2a_local <<<dim3(NC2, PD / 8, BSZ), 256>>>(Are, Aim);
    k2b_carry <<<BSZ, 256>>>(Are, Aim);
    k2c_replay<<<dim3(NC2, PD / 8, BSZ), 256>>>(Are, Aim);
    k3_out    <<<dim3(LSEQ / 128, BSZ), 256>>>(u, out);
}

// round 3
// speedup vs baseline: 3.2816x; 2.0098x over previous
#include <cuda_runtime.h>
#include <cuda_bf16.h>
#include <math.h>

#define BSZ   8
#define HD    128
#define LSEQ  8192
#define PD    256
#define NC2   16
#define CL    (LSEQ / NC2)   // 512 per chunk

// ---------------- scratch (__device__ globals) ----------------
__device__ __align__(16) float g_br[(size_t)BSZ * PD * LSEQ];   // Bu real -> x real
__device__ __align__(16) float g_bi[(size_t)BSZ * PD * LSEQ];   // Bu imag -> x imag
__device__ float2 g_E[BSZ * NC2 * PD];
__device__ float2 g_carry[BSZ * NC2 * PD];
// Pre-packed A fragments (per-lane uint4): [m16blk][ks][hi/lo][lane]
__device__ __align__(16) uint4 g_WbPk[32 * 8  * 2 * 32];   // Wb: M=512, K=128
__device__ __align__(16) uint4 g_WcPk[8  * 40 * 2 * 32];   // Wc: M=128, K=640

__device__ __forceinline__ float2 cmul(float2 a, float2 b) {
    return make_float2(a.x * b.x - a.y * b.y, a.x * b.y + a.y * b.x);
}
__device__ __forceinline__ void split2(float v, __nv_bfloat16* hi, __nv_bfloat16* lo) {
    __nv_bfloat16 h = __float2bfloat16(v);
    *hi = h;
    *lo = __float2bfloat16(v - __bfloat162float(h));
}
__device__ __forceinline__ unsigned pack_split(float w0, float w1, int hl) {
    __nv_bfloat16 h0, l0, h1, l1;
    split2(w0, &h0, &l0); split2(w1, &h1, &l1);
    unsigned a = __bfloat16_as_ushort(hl ? l0 : h0);
    unsigned b = __bfloat16_as_ushort(hl ? l1 : h1);
    return a | (b << 16);
}
__device__ __forceinline__ unsigned pack_hi(float w0, float w1) {
    return (unsigned)__bfloat16_as_ushort(__float2bfloat16(w0)) |
           ((unsigned)__bfloat16_as_ushort(__float2bfloat16(w1)) << 16);
}
__device__ __forceinline__ unsigned pack_lo(float w0, float w1) {
    __nv_bfloat16 h0 = __float2bfloat16(w0), h1 = __float2bfloat16(w1);
    float r0 = w0 - __bfloat162float(h0), r1 = w1 - __bfloat162float(h1);
    return (unsigned)__bfloat16_as_ushort(__float2bfloat16(r0)) |
           ((unsigned)__bfloat16_as_ushort(__float2bfloat16(r1)) << 16);
}
__device__ __forceinline__ void mma_bf16(float c[4], const unsigned a[4], unsigned b0, unsigned b1) {
    asm volatile(
        "mma.sync.aligned.m16n8k16.row.col.f32.bf16.bf16.f32 "
        "{%0,%1,%2,%3}, {%4,%5,%6,%7}, {%8,%9}, {%0,%1,%2,%3};"
        : "+f"(c[0]), "+f"(c[1]), "+f"(c[2]), "+f"(c[3])
        : "r"(a[0]), "r"(a[1]), "r"(a[2]), "r"(a[3]), "r"(b0), "r"(b1));
}
__device__ __forceinline__ void ldsm_x4_t(unsigned r[4], unsigned addr) {
    asm volatile("ldmatrix.sync.aligned.m8n8.x4.trans.shared.b16 {%0,%1,%2,%3}, [%4];"
                 : "=r"(r[0]), "=r"(r[1]), "=r"(r[2]), "=r"(r[3]) : "r"(addr));
}
__device__ __forceinline__ unsigned smem_u32(const void* p) {
    unsigned a;
    asm("{ .reg .u64 t; cvta.to.shared.u64 t, %1; cvt.u32.u64 %0, t; }" : "=r"(a) : "l"(p));
    return a;
}

// ---------------------------------------------------------------------------
// K0: pack weights into per-lane mma A-fragments (hi/lo split).
// ---------------------------------------------------------------------------
__device__ __forceinline__ float wb_get(int r, int c, const float* Bre, const float* Bim) {
    return (r < 256) ? Bre[r * 128 + c] : Bim[(r - 256) * 128 + c];
}
__device__ __forceinline__ float wc_get(int o, int k, const float* Cre, const float* Cim,
                                        const float* Dm) {
    if (k < 256) return Cre[o * 256 + k];
    if (k < 512) return -Cim[o * 256 + (k - 256)];
    return Dm[o * 128 + (k - 512)];
}
__global__ void __launch_bounds__(256) k0_prep(
    const float* __restrict__ Bre, const float* __restrict__ Bim,
    const float* __restrict__ Cre, const float* __restrict__ Cim,
    const float* __restrict__ Dm)
{
    int idx = blockIdx.x * 256 + threadIdx.x;
    if (idx < 32 * 8 * 2 * 32) {
        int lane = idx & 31, hl = (idx >> 5) & 1, ks = (idx >> 6) & 7, blk = idx >> 9;
        int r = blk * 16 + (lane >> 2);
        int cb = ks * 16 + (lane & 3) * 2;
        uint4 o;
        o.x = pack_split(wb_get(r,     cb,     Bre, Bim), wb_get(r,     cb + 1, Bre, Bim), hl);
        o.y = pack_split(wb_get(r + 8, cb,     Bre, Bim), wb_get(r + 8, cb + 1, Bre, Bim), hl);
        o.z = pack_split(wb_get(r,     cb + 8, Bre, Bim), wb_get(r,     cb + 9, Bre, Bim), hl);
        o.w = pack_split(wb_get(r + 8, cb + 8, Bre, Bim), wb_get(r + 8, cb + 9, Bre, Bim), hl);
        g_WbPk[idx] = o;
    }
    if (idx < 8 * 40 * 2 * 32) {
        int lane = idx & 31, hl = (idx >> 5) & 1, t = idx >> 6;
        int ks = t % 40, blk = t / 40;
        int r = blk * 16 + (lane >> 2);
        int cb = ks * 16 + (lane & 3) * 2;
        uint4 o;
        o.x = pack_split(wc_get(r,     cb,     Cre, Cim, Dm), wc_get(r,     cb + 1, Cre, Cim, Dm), hl);
        o.y = pack_split(wc_get(r + 8, cb,     Cre, Cim, Dm), wc_get(r + 8, cb + 1, Cre, Cim, Dm), hl);
        o.z = pack_split(wc_get(r,     cb + 8, Cre, Cim, Dm), wc_get(r,     cb + 9, Cre, Cim, Dm), hl);
        o.w = pack_split(wc_get(r + 8, cb + 8, Cre, Cim, Dm), wc_get(r + 8, cb + 9, Cre, Cim, Dm), hl);
        g_WcPk[idx] = o;
    }
}

// ---------------------------------------------------------------------------
// Shared gemm machinery: smem staged as [k(64)][l(128)] bf16 hi+lo, pad 136.
// B frags via ldmatrix.x4.trans, A frags via packed LDG.128.
// ---------------------------------------------------------------------------
#define SROW 136

__device__ __forceinline__ void stage_sts(__nv_bfloat16 (*sh)[SROW], __nv_bfloat16 (*sl)[SROW],
                                          const float4 v[8], int srr, int sl4)
{
#pragma unroll
    for (int t = 0; t < 8; t++) {
        int rr = srr + t * 8;
        uint2 ph, pl;
        ph.x = pack_hi(v[t].x, v[t].y); ph.y = pack_hi(v[t].z, v[t].w);
        pl.x = pack_lo(v[t].x, v[t].y); pl.y = pack_lo(v[t].z, v[t].w);
        *(uint2*)&sh[rr][sl4] = ph;
        *(uint2*)&sl[rr][sl4] = pl;
    }
}

// mma over one staged 64k x 128l chunk. weights: packed frag array, blkbase = m16blk of (wm,mi=0)
__device__ __forceinline__ void mma_chunk(float c[2][8][4], const uint4* wpk, int ks_stride,
                                          int blk0, int blk1, int ksg0,
                                          unsigned sh_base, unsigned sl_base,
                                          int lane, int wn)
{
    const int brow = (lane & 7) + (lane & 8);            // ldmatrix row within 16-k block
    const int bcol = ((lane >> 4) << 3);                 // +8 n for upper matrices
#pragma unroll
    for (int ks = 0; ks < 4; ks++) {
        const int km = ks * 16;
        const int ksg = ksg0 + ks;
        uint4 ah0 = wpk[((blk0 * ks_stride + ksg) * 2 + 0) * 32 + lane];
        uint4 al0 = wpk[((blk0 * ks_stride + ksg) * 2 + 1) * 32 + lane];
        uint4 ah1 = wpk[((blk1 * ks_stride + ksg) * 2 + 0) * 32 + lane];
        uint4 al1 = wpk[((blk1 * ks_stride + ksg) * 2 + 1) * 32 + lane];
#pragma unroll
        for (int ng = 0; ng < 4; ng++) {
            int n0 = wn * 64 + ng * 16;
            unsigned off = (unsigned)(((km + brow) * SROW + n0 + bcol) * 2);
            unsigned bh[4], bl[4];
            ldsm_x4_t(bh, sh_base + off);
            ldsm_x4_t(bl, sl_base + off);
            // mi = 0
            mma_bf16(c[0][ng * 2 + 0], (const unsigned*)&ah0, bh[0], bh[1]);
            mma_bf16(c[0][ng * 2 + 0], (const unsigned*)&ah0, bl[0], bl[1]);
            mma_bf16(c[0][ng * 2 + 0], (const unsigned*)&al0, bh[0], bh[1]);
            mma_bf16(c[0][ng * 2 + 1], (const unsigned*)&ah0, bh[2], bh[3]);
            mma_bf16(c[0][ng * 2 + 1], (const unsigned*)&ah0, bl[2], bl[3]);
            mma_bf16(c[0][ng * 2 + 1], (const unsigned*)&al0, bh[2], bh[3]);
            // mi = 1
            mma_bf16(c[1][ng * 2 + 0], (const unsigned*)&ah1, bh[0], bh[1]);
            mma_bf16(c[1][ng * 2 + 0], (const unsigned*)&ah1, bl[0], bl[1]);
            mma_bf16(c[1][ng * 2 + 0], (const unsigned*)&al1, bh[0], bh[1]);
            mma_bf16(c[1][ng * 2 + 1], (const unsigned*)&ah1, bh[2], bh[3]);
            mma_bf16(c[1][ng * 2 + 1], (const unsigned*)&ah1, bl[2], bl[3]);
            mma_bf16(c[1][ng * 2 + 1], (const unsigned*)&al1, bh[2], bh[3]);
        }
    }
}

// ---------------------------------------------------------------------------
// K1: [Bre;Bim](512x128) @ u(128 x L) -> planar g_br/g_bi.  grid (L/128, 4, BSZ)
// ---------------------------------------------------------------------------
__global__ void __launch_bounds__(256) k1_bu(const float* __restrict__ u)
{
    __shared__ __align__(16) __nv_bfloat16 sh[64][SROW];
    __shared__ __align__(16) __nv_bfloat16 sl[64][SROW];

    const int b = blockIdx.z, lbase = blockIdx.x * 128, mt = blockIdx.y;
    const int tid = threadIdx.x, lane = tid & 31, wid = tid >> 5;
    const int wm = wid >> 1, wn = wid & 1;
    const int srr = tid >> 5, sl4 = (tid & 31) * 4;
    const unsigned sh_base = smem_u32(&sh[0][0]);
    const unsigned sl_base = smem_u32(&sl[0][0]);

    float c[2][8][4];
#pragma unroll
    for (int mi = 0; mi < 2; mi++)
#pragma unroll
        for (int ni = 0; ni < 8; ni++)
#pragma unroll
            for (int q = 0; q < 4; q++) c[mi][ni][q] = 0.f;

    const float* ubase = u + (size_t)b * HD * LSEQ + lbase;
    float4 v[8];
#pragma unroll
    for (int t = 0; t < 8; t++)
        v[t] = *(const float4*)(ubase + (size_t)(srr + t * 8) * LSEQ + sl4);

    const int blk0 = mt * 8 + wm * 2;
#pragma unroll
    for (int cch = 0; cch < 2; cch++) {
        stage_sts(sh, sl, v, srr, sl4);
        __syncthreads();
        if (cch == 0) {
#pragma unroll
            for (int t = 0; t < 8; t++)
                v[t] = *(const float4*)(ubase + (size_t)(64 + srr + t * 8) * LSEQ + sl4);
        }
        mma_chunk(c, g_WbPk, 8, blk0, blk0 + 1, cch * 4, sh_base, sl_base, lane, wn);
        __syncthreads();
    }

    // epilogue: planar float2 stores
#pragma unroll
    for (int mi = 0; mi < 2; mi++) {
#pragma unroll
        for (int ni = 0; ni < 8; ni++) {
            int r0  = mt * 128 + wm * 32 + mi * 16 + (lane >> 2);
            int col = lbase + wn * 64 + ni * 8 + (lane & 3) * 2;
            {
                float* plane = (r0 < 256) ? g_br : g_bi;
                int pr = (r0 < 256) ? r0 : r0 - 256;
                *(float2*)&plane[((size_t)b * PD + pr) * LSEQ + col] =
                    make_float2(c[mi][ni][0], c[mi][ni][1]);
            }
            int r1 = r0 + 8;
            {
                float* plane = (r1 < 256) ? g_br : g_bi;
                int pr = (r1 < 256) ? r1 : r1 - 256;
                *(float2*)&plane[((size_t)b * PD + pr) * LSEQ + col] =
                    make_float2(c[mi][ni][2], c[mi][ni][3]);
            }
        }
    }
}

// ---------------------------------------------------------------------------
// K2 warp-scan (unchanged from R2, passing)
// ---------------------------------------------------------------------------
__device__ __forceinline__ void lane_powers(float2 a, int lane, float2* ap, float2* w1m)
{
    float invn = 1.f / (a.x * a.x + a.y * a.y);
    float2 ainv = make_float2(a.x * invn, -a.y * invn);
    float2 pp = make_float2(1.f, 0.f), pn = make_float2(1.f, 0.f);
    float2 t = a, ti = ainv;
#pragma unroll
    for (int bit = 1; bit < 32; bit <<= 1) {
        if (lane & bit) { pp = cmul(pp, t); pn = cmul(pn, ti); }
        t = cmul(t, t); ti = cmul(ti, ti);
    }
    *ap = pp; *w1m = cmul(a, pn);
}

template <bool WRITE_X, bool LOAD_CARRY>
__device__ __forceinline__ void scan_chunk(const float* Are, const float* Aim)
{
    const int b = blockIdx.z, c = blockIdx.x;
    const int wid = threadIdx.x >> 5, lane = threadIdx.x & 31;
    const int p = blockIdx.y * 8 + wid;
    const float2 a = make_float2(Are[p], Aim[p]);
    float2 ap, w1m;
    lane_powers(a, lane, &ap, &w1m);

    const size_t base = ((size_t)b * PD + p) * LSEQ + (size_t)c * CL;
    float2 carry = make_float2(0.f, 0.f);
    if (LOAD_CARRY) carry = g_carry[(b * NC2 + c) * PD + p];

#pragma unroll 4
    for (int s = 0; s < CL / 32; s++) {
        size_t idx = base + s * 32 + lane;
        float br = g_br[idx], bi = g_bi[idx];
        float2 w = make_float2(br * w1m.x - bi * w1m.y, br * w1m.y + bi * w1m.x);
#pragma unroll
        for (int d = 1; d < 32; d <<= 1) {
            float ox = __shfl_up_sync(0xffffffffu, w.x, d);
            float oy = __shfl_up_sync(0xffffffffu, w.y, d);
            if (lane >= d) { w.x += ox; w.y += oy; }
        }
        float2 ac = cmul(a, carry);
        float2 x  = cmul(ap, make_float2(ac.x + w.x, ac.y + w.y));
        if (WRITE_X) { g_br[idx] = x.x; g_bi[idx] = x.y; }
        carry.x = __shfl_sync(0xffffffffu, x.x, 31);
        carry.y = __shfl_sync(0xffffffffu, x.y, 31);
    }
    if (!WRITE_X && lane == 0)
        g_E[(b * NC2 + c) * PD + p] = carry;
}

__global__ void __launch_bounds__(256) k2a_local(
    const float* __restrict__ Are, const float* __restrict__ Aim)
{ scan_chunk<false, false>(Are, Aim); }

__global__ void __launch_bounds__(256) k2c_replay(
    const float* __restrict__ Are, const float* __restrict__ Aim)
{ scan_chunk<true, true>(Are, Aim); }

__global__ void __launch_bounds__(256) k2b_carry(
    const float* __restrict__ Are, const float* __restrict__ Aim)
{
    const int b = blockIdx.x, p = threadIdx.x;
    float2 a = make_float2(Are[p], Aim[p]);
    float2 aT = a;
#pragma unroll
    for (int k = 0; k < 9; k++) aT = cmul(aT, aT);   // a^512
    float2 E[NC2];
#pragma unroll
    for (int c = 0; c < NC2; c++) E[c] = g_E[(b * NC2 + c) * PD + p];  // MLP prefetch
    float2 S = make_float2(0.f, 0.f);
#pragma unroll
    for (int c = 0; c < NC2; c++) {
        g_carry[(b * NC2 + c) * PD + p] = S;
        S = make_float2(aT.x * S.x - aT.y * S.y + E[c].x,
                        aT.x * S.y + aT.y * S.x + E[c].y);
    }
}

// ---------------------------------------------------------------------------
// K3: [Cre|-Cim|D](128x640) @ [x_re;x_im;u](640 x L) + GELU.  grid (L/128, BSZ)
// ---------------------------------------------------------------------------
__global__ void __launch_bounds__(256) k3_out(const float* __restrict__ u,
                                              float* __restrict__ out)
{
    __shared__ __align__(16) __nv_bfloat16 sh[64][SROW];
    __shared__ __align__(16) __nv_bfloat16 sl[64][SROW];

    const int b = blockIdx.y, lbase = blockIdx.x * 128;
    const int tid = threadIdx.x, lane = tid & 31, wid = tid >> 5;
    const int wm = wid >> 1, wn = wid & 1;
    const int srr = tid >> 5, sl4 = (tid & 31) * 4;
    const unsigned sh_base = smem_u32(&sh[0][0]);
    const unsigned sl_base = smem_u32(&sl[0][0]);

    float c[2][8][4];
#pragma unroll
    for (int mi = 0; mi < 2; mi++)
#pragma unroll
        for (int ni = 0; ni < 8; ni++)
#pragma unroll
            for (int q = 0; q < 4; q++) c[mi][ni][q] = 0.f;

    auto srcp = [&](int kc) -> const float* {
        if (kc < 256) return g_br + ((size_t)b * PD + kc) * LSEQ + lbase;
        if (kc < 512) return g_bi + ((size_t)b * PD + (kc - 256)) * LSEQ + lbase;
        return u + ((size_t)b * HD + (kc - 512)) * LSEQ + lbase;
    };

    float4 v[8];
    {
        const float* s0 = srcp(0);
#pragma unroll
        for (int t = 0; t < 8; t++)
            v[t] = *(const float4*)(s0 + (size_t)(srr + t * 8) * LSEQ + sl4);
    }

    const int blk0 = wm * 2;
    for (int cch = 0; cch < 10; cch++) {
        stage_sts(sh, sl, v, srr, sl4);
        __syncthreads();
        if (cch < 9) {
            const float* s = srcp((cch + 1) * 64);
#pragma unroll
            for (int t = 0; t < 8; t++)
                v[t] = *(const float4*)(s + (size_t)(srr + t * 8) * LSEQ + sl4);
        }
        mma_chunk(c, g_WcPk, 40, blk0, blk0 + 1, cch * 4, sh_base, sl_base, lane, wn);
        __syncthreads();
    }

    // epilogue: exact-erf GELU, float2 stores
#pragma unroll
    for (int mi = 0; mi < 2; mi++) {
#pragma unroll
        for (int ni = 0; ni < 8; ni++) {
            int r0  = wm * 32 + mi * 16 + (lane >> 2);
            int col = lbase + wn * 64 + ni * 8 + (lane & 3) * 2;
            float y0 = c[mi][ni][0], y1 = c[mi][ni][1];
            float y2 = c[mi][ni][2], y3 = c[mi][ni][3];
            y0 = 0.5f * y0 * (1.f + erff(y0 * 0.70710678118654752f));
            y1 = 0.5f * y1 * (1.f + erff(y1 * 0.70710678118654752f));
            y2 = 0.5f * y2 * (1.f + erff(y2 * 0.70710678118654752f));
            y3 = 0.5f * y3 * (1.f + erff(y3 * 0.70710678118654752f));
            *(float2*)&out[((size_t)b * HD + r0) * LSEQ + col]     = make_float2(y0, y1);
            *(float2*)&out[((size_t)b * HD + r0 + 8) * LSEQ + col] = make_float2(y2, y3);
        }
    }
}

// ---------------------------------------------------------------------------
extern "C" void kernel_launch(void* const* d_in, const int* in_sizes, int n_in,
                              void* d_out, int out_size)
{
    (void)in_sizes; (void)n_in; (void)out_size;
    const float* u   = (const float*)d_in[0];
    const float* Are = (const float*)d_in[1];
    const float* Aim = (const float*)d_in[2];
    const float* Bre = (const float*)d_in[3];
    const float* Bim = (const float*)d_in[4];
    const float* Cre = (const float*)d_in[5];
    const float* Cim = (const float*)d_in[6];
    const float* Dm  = (const float*)d_in[7];
    float* out = (float*)d_out;

    k0_prep   <<<80, 256>>>(Bre, Bim, Cre, Cim, Dm);
    k1_bu     <<<dim3(LSEQ / 128, 4, BSZ), 256>>>(u);
    k2a_local <<<dim3(NC2, PD / 8, BSZ), 256>>>(Are, Aim);
    k2b_carry <<<BSZ, 256>>>(Are, Aim);
    k2c_replay<<<dim3(NC2, PD / 8, BSZ), 256>>>(Are, Aim);
    k3_out    <<<dim3(LSEQ / 128, BSZ), 256>>>(u, out);
}